// round 12
// baseline (speedup 1.0000x reference)
#include <cuda_runtime.h>
#include <cstddef>

#define FULL_MASK 0xffffffffu

// ---------------------------------------------------------------------------
// packed fp32x2 FMA (sm_100+)
// ---------------------------------------------------------------------------
__device__ __forceinline__ float2 ffma2(float2 a, float2 b, float2 c) {
    unsigned long long ua = *reinterpret_cast<unsigned long long*>(&a);
    unsigned long long ub = *reinterpret_cast<unsigned long long*>(&b);
    unsigned long long uc = *reinterpret_cast<unsigned long long*>(&c);
    unsigned long long ud;
    asm("fma.rn.f32x2 %0, %1, %2, %3;" : "=l"(ud) : "l"(ua), "l"(ub), "l"(uc));
    return *reinterpret_cast<float2*>(&ud);
}

// L2-coherent load: g_xg is produced by other SMs during this kernel.
__device__ __forceinline__ float ldcg(const float* p) {
    float v; asm volatile("ld.global.cg.f32 %0, [%1];" : "=f"(v) : "l"(p)); return v;
}

__device__ __forceinline__ float sigf(float x) {
    return __fdividef(1.0f, 1.0f + __expf(-x));
}
__device__ __forceinline__ float tanh_fast(float x) {
    return 2.0f * sigf(2.0f * x) - 1.0f;
}

// Scratch: precomputed layer-1 input gates XG[B*T][256]  (64 MB)
__device__ float g_xg[64 * 1024 * 256];
// Per-m-tile completion flags: y = batch*8 + chunk; ready when flag[y] == 2
__device__ int g_flag[512];

// ---------------------------------------------------------------------------
// Fused kernel, 768 threads/CTA.
//   blockIdx.x < 64   -> scan CTA (one batch): 3 thread-groups, one weight
//                        matrix each (64 regs/thread), 2 barriers/step.
//   blockIdx.x >= 64  -> GEMM CTA (512 of 768 threads, chunk-major order)
// ---------------------------------------------------------------------------
__global__ __launch_bounds__(768, 1) void fused_kernel(
    const float* __restrict__ X,
    const float* __restrict__ w1_ih0, const float* __restrict__ w1_hh0,
    const float* __restrict__ b1_0,
    const float* __restrict__ w1_ih1, const float* __restrict__ w1_hh1,
    const float* __restrict__ b1_1,
    const float* __restrict__ w2_ih0, const float* __restrict__ w2_hh0,
    const float* __restrict__ b2_0,
    const float* __restrict__ w2_ih1, const float* __restrict__ w2_hh1,
    const float* __restrict__ b2_1,
    const float* __restrict__ fc_w,  const float* __restrict__ fc_b,
    float* __restrict__ out)
{
    // ================= GEMM branch =================
    if (blockIdx.x >= 64) {
        __shared__ float As[16][132];
        __shared__ float Bs[16][132];
        const int gi = blockIdx.x - 64;          // 0..1023
        const int xnt = gi & 1;
        const int r  = gi >> 1;
        const int chunk = r >> 6;                // chunk-major order
        const int batch = r & 63;
        const int y  = batch * 8 + chunk;
        const int m0 = y * 128;
        const int n0 = xnt * 128;
        const int tid = threadIdx.x;
        const bool act = (tid < 512);
        const int tx = tid & 31;                 // 4 cols each
        const int ty = tid >> 5;                 // 8 rows each (0..15)

        float2 c[8][2];
#pragma unroll
        for (int i = 0; i < 8; i++) { c[i][0] = make_float2(0.f, 0.f); c[i][1] = c[i][0]; }

        for (int k0 = 0; k0 < 512; k0 += 16) {
            if (act) {
                int row = tid >> 2;              // 0..127
                int kq  = (tid & 3) << 2;        // 0,4,8,12
                float4 va = *reinterpret_cast<const float4*>(&X[(size_t)(m0 + row) * 512 + k0 + kq]);
                As[kq + 0][row] = va.x; As[kq + 1][row] = va.y;
                As[kq + 2][row] = va.z; As[kq + 3][row] = va.w;
                float4 vb = *reinterpret_cast<const float4*>(&w1_ih0[(size_t)(n0 + row) * 512 + k0 + kq]);
                Bs[kq + 0][row] = vb.x; Bs[kq + 1][row] = vb.y;
                Bs[kq + 2][row] = vb.z; Bs[kq + 3][row] = vb.w;
            }
            __syncthreads();
            if (act) {
#pragma unroll
                for (int kk = 0; kk < 16; kk++) {
                    float4 a0 = *reinterpret_cast<const float4*>(&As[kk][ty * 8]);
                    float4 a1 = *reinterpret_cast<const float4*>(&As[kk][ty * 8 + 4]);
                    float4 bv = *reinterpret_cast<const float4*>(&Bs[kk][tx * 4]);
                    float  a[8]  = {a0.x, a0.y, a0.z, a0.w, a1.x, a1.y, a1.z, a1.w};
                    float2 b0 = make_float2(bv.x, bv.y);
                    float2 b1 = make_float2(bv.z, bv.w);
#pragma unroll
                    for (int i = 0; i < 8; i++) {
                        float2 aa = make_float2(a[i], a[i]);
                        c[i][0] = ffma2(aa, b0, c[i][0]);
                        c[i][1] = ffma2(aa, b1, c[i][1]);
                    }
                }
            }
            __syncthreads();
        }

        if (act) {
            float4 bv = *reinterpret_cast<const float4*>(&b1_0[n0 + tx * 4]);
#pragma unroll
            for (int i = 0; i < 8; i++) {
                int m = m0 + ty * 8 + i;
                float4 o = make_float4(c[i][0].x + bv.x, c[i][0].y + bv.y,
                                       c[i][1].x + bv.z, c[i][1].y + bv.w);
                *reinterpret_cast<float4*>(&g_xg[(size_t)m * 256 + n0 + tx * 4]) = o;
            }
        }
        __syncthreads();
        if (tid == 0) {
            __threadfence();
            atomicAdd(&g_flag[y], 1);
        }
        return;
    }

    // ================= scan branch: 768 threads, 3 groups =================
    // group A: t in [0,256)    -> wA = w1_hh0 rows, xg, cell1 on t<64
    // group B: t in [256,512)  -> wB = w1_ih1 rows (+bias), cell2 on t-256<64
    // group C: t in [512,768)  -> wC = w1_hh1 rows; warp 16 runs L3/L4/FC tail
    __shared__ float sh_h1[64];
    __shared__ float sh_h2[2][64];       // parity-double-buffered
    __shared__ float sh_pre1[256];
    __shared__ float sh_preB[256];
    __shared__ float sh_preC[256];
    // tail weights (R5-proven layout)
    __shared__ float2 sh_w2ih0T2[32 * 32];
    __shared__ float  sh_w2hh0T[6 * 32];
    __shared__ float  sh_w2ih1T[6 * 32];
    __shared__ float  sh_w2hh1T[6 * 32];
    __shared__ float  sh_fcw[36];
    __shared__ float  sh_b20[32];
    __shared__ float  sh_b21[32];
    __shared__ float  sh_fcb[8];
    __shared__ float  sh_h3[8];
    __shared__ float  sh_h4[8];

    const int t = threadIdx.x;
    const int b = blockIdx.x;
    const int yb = b * 8;
    const int grp = t >> 8;              // 0,1,2
    const int r   = t & 255;             // row within this group's matrix

    // one weight matrix row per thread (64 regs)
    float2 w[32];
    {
        const float* src = (grp == 0) ? w1_hh0 : (grp == 1) ? w1_ih1 : w1_hh1;
        const float2* p = reinterpret_cast<const float2*>(src) + r * 32;
#pragma unroll
        for (int i = 0; i < 32; i++) w[i] = p[i];
    }
    const float bias11 = (grp == 1) ? b1_1[r] : 0.f;

    // ---- init shared state / tail weights ----
    if (t < 64) sh_h1[t] = 0.f;
    if (t >= 64 && t < 192) { int e = t - 64; sh_h2[e >> 6][e & 63] = 0.f; }
    if (t >= 192 && t < 200) { sh_h3[t - 192] = 0.f; sh_h4[t - 192] = 0.f; }
    if (t >= 200 && t < 208) sh_fcb[t - 200] = (t - 200 < 6) ? fc_b[t - 200] : 0.f;
    for (int i = t; i < 1024; i += 768) {
        int k2 = i >> 5, l = i & 31;
        sh_w2ih0T2[i] = (l < 24)
            ? make_float2(w2_ih0[l * 64 + 2 * k2], w2_ih0[l * 64 + 2 * k2 + 1])
            : make_float2(0.f, 0.f);
    }
    if (t >= 256 && t < 448) {
        int i = t - 256;
        int k = i / 32, l = i & 31;
        sh_w2hh0T[i] = (l < 24) ? w2_hh0[l * 6 + k] : 0.f;
        sh_w2ih1T[i] = (l < 24) ? w2_ih1[l * 6 + k] : 0.f;
        sh_w2hh1T[i] = (l < 24) ? w2_hh1[l * 6 + k] : 0.f;
    }
    if (t >= 448 && t < 484) sh_fcw[t - 448] = fc_w[t - 448];
    if (t >= 484 && t < 516) {
        int l = t - 484;
        sh_b20[l] = (l < 24) ? b2_0[l] : 0.f;
        sh_b21[l] = (l < 24) ? b2_1[l] : 0.f;
    }

    // wait for chunk 0
    if (t == 0) {
        while (atomicAdd(&g_flag[yb], 0) < 2) __nanosleep(64);
        __threadfence();
    }
    __syncthreads();

    float c1 = 0.f, c2 = 0.f, c3 = 0.f, c4 = 0.f;
    const float* xg = g_xg + ((size_t)b << 10) * 256;
    float*      outp = out + ((size_t)b << 10) * 6;

    // ---- prologue: h1(0) = cell1(xg(0)) ----
    if (t < 256) sh_pre1[t] = ldcg(&xg[t]);
    __syncthreads();
    if (t < 64) {
        float gi = sigf(sh_pre1[t]);
        float gf = sigf(sh_pre1[64 + t]);
        float gg = tanh_fast(sh_pre1[128 + t]);
        float go = sigf(sh_pre1[192 + t]);
        c1 = gf * c1 + gi * gg;
        sh_h1[t] = go * tanh_fast(c1);
    }
    __syncthreads();
    float xg_cur = 0.f, xg_next = 0.f;
    if (t < 256) xg_next = ldcg(&xg[256 + t]);   // row 1

    // iter k: A: pre1(k+1)=wA@h1(k)+xg(k+1); preB=wB@h1(k)+bias; preC=wC@h2(k-1)
    //         B: cell1 -> h1(k+1); cell2 -> h2(k); warp16 tail for step k-1
    for (int k = 0; k <= 1024; k++) {
        if (k < 1024) {
            // chunk gate for prefetch of row k+2 (uniform condition)
            if (k + 2 < 1024 && ((k + 2) & 127) == 0) {
                if (t == 0) {
                    int yc = yb + ((k + 2) >> 7);
                    while (atomicAdd(&g_flag[yc], 0) < 2) __nanosleep(64);
                    __threadfence();
                }
                __syncthreads();
            }
            if (t < 256) {
                xg_cur = xg_next;
                if (k + 2 < 1024) xg_next = ldcg(&xg[(size_t)(k + 2) * 256 + t]);
            }

            // ---- phase A: one dot per thread ----
            const float* hs = (grp < 2) ? sh_h1 : sh_h2[(k + 1) & 1];  // h2(k-1)
            float2 a0 = make_float2(0.f, 0.f), a1 = a0, a2 = a0, a3 = a0;
            const float4* hp = reinterpret_cast<const float4*>(hs);
#pragma unroll
            for (int k4 = 0; k4 < 16; k4 += 2) {
                float4 ha = hp[k4];
                float4 hb = hp[k4 + 1];
                a0 = ffma2(w[2 * k4 + 0], make_float2(ha.x, ha.y), a0);
                a1 = ffma2(w[2 * k4 + 1], make_float2(ha.z, ha.w), a1);
                a2 = ffma2(w[2 * k4 + 2], make_float2(hb.x, hb.y), a2);
                a3 = ffma2(w[2 * k4 + 3], make_float2(hb.z, hb.w), a3);
            }
            float v = ((a0.x + a0.y) + (a1.x + a1.y)) + ((a2.x + a2.y) + (a3.x + a3.y));
            if (grp == 0)      sh_pre1[r] = v + xg_cur;
            else if (grp == 1) sh_preB[r] = v + bias11;
            else               sh_preC[r] = v;
        }
        __syncthreads();   // SA

        // ---- phase B ----
        if (k < 1024) {
            if (t < 64) {
                // cell1 -> h1(k+1)
                float gi = sigf(sh_pre1[t]);
                float gf = sigf(sh_pre1[64 + t]);
                float gg = tanh_fast(sh_pre1[128 + t]);
                float go = sigf(sh_pre1[192 + t]);
                c1 = gf * c1 + gi * gg;
                sh_h1[t] = go * tanh_fast(c1);
            } else if (t >= 256 && t < 320) {
                // cell2 -> h2(k)
                const int e = t - 256;
                float gi = sigf(sh_preB[e]       + sh_preC[e]);
                float gf = sigf(sh_preB[64 + e]  + sh_preC[64 + e]);
                float gg = tanh_fast(sh_preB[128 + e] + sh_preC[128 + e]);
                float go = sigf(sh_preB[192 + e] + sh_preC[192 + e]);
                c2 = gf * c2 + gi * gg;
                sh_h2[k & 1][e] = go * tanh_fast(c2);
            }
        }
        // tail: warp 16 processes step k-1 (reads h2[(k-1)&1], stable)
        if (k >= 1 && t >= 512 && t < 544) {
            const int l = t & 31;
            const float2* h2p = reinterpret_cast<const float2*>(sh_h2[(k + 1) & 1]);
            float2 a0 = make_float2(0.f, 0.f), a1 = make_float2(0.f, 0.f);
#pragma unroll
            for (int k2 = 0; k2 < 32; k2 += 2) {
                a0 = ffma2(sh_w2ih0T2[k2 * 32 + l],       h2p[k2],     a0);
                a1 = ffma2(sh_w2ih0T2[(k2 + 1) * 32 + l], h2p[k2 + 1], a1);
            }
            float acc = a0.x + a0.y + a1.x + a1.y + sh_b20[l];
#pragma unroll
            for (int kk = 0; kk < 6; kk++) acc += sh_w2hh0T[kk * 32 + l] * sh_h3[kk];
            float vf = __shfl_sync(FULL_MASK, acc, (l + 6) & 31);
            float vg = __shfl_sync(FULL_MASK, acc, (l + 12) & 31);
            float vo = __shfl_sync(FULL_MASK, acc, (l + 18) & 31);
            if (l < 6) {
                float gi = sigf(acc), gf = sigf(vf);
                float gg = tanh_fast(vg), go = sigf(vo);
                c3 = gf * c3 + gi * gg;
                sh_h3[l] = go * tanh_fast(c3);
            }
            __syncwarp();
            float acc4 = sh_b21[l];
#pragma unroll
            for (int kk = 0; kk < 6; kk++) {
                acc4 += sh_w2ih1T[kk * 32 + l] * sh_h3[kk];
                acc4 += sh_w2hh1T[kk * 32 + l] * sh_h4[kk];
            }
            float wf = __shfl_sync(FULL_MASK, acc4, (l + 6) & 31);
            float wg = __shfl_sync(FULL_MASK, acc4, (l + 12) & 31);
            float wo = __shfl_sync(FULL_MASK, acc4, (l + 18) & 31);
            __syncwarp();
            if (l < 6) {
                float gi = sigf(acc4), gf = sigf(wf);
                float gg = tanh_fast(wg), go = sigf(wo);
                c4 = gf * c4 + gi * gg;
                sh_h4[l] = go * tanh_fast(c4);
            }
            __syncwarp();
            if (l < 6) {
                float o = sh_fcb[l];
#pragma unroll
                for (int kk = 0; kk < 6; kk++) o += sh_fcw[l * 6 + kk] * sh_h4[kk];
                outp[(size_t)(k - 1) * 6 + l] = o;
            }
        }
        __syncthreads();   // SB
    }
}

// ---------------------------------------------------------------------------
extern "C" void kernel_launch(void* const* d_in, const int* in_sizes, int n_in,
                              void* d_out, int out_size) {
    const float* x      = (const float*)d_in[0];
    const float* w1_ih0 = (const float*)d_in[1];
    const float* w1_hh0 = (const float*)d_in[2];
    const float* b1_0   = (const float*)d_in[3];
    const float* w1_ih1 = (const float*)d_in[4];
    const float* w1_hh1 = (const float*)d_in[5];
    const float* b1_1   = (const float*)d_in[6];
    const float* w2_ih0 = (const float*)d_in[7];
    const float* w2_hh0 = (const float*)d_in[8];
    const float* b2_0   = (const float*)d_in[9];
    const float* w2_ih1 = (const float*)d_in[10];
    const float* w2_hh1 = (const float*)d_in[11];
    const float* b2_1   = (const float*)d_in[12];
    const float* fc_w   = (const float*)d_in[13];
    const float* fc_b   = (const float*)d_in[14];
    float* out = (float*)d_out;

    // reset GEMM-tile completion flags (graph-capturable memset node)
    void* flag_ptr = nullptr;
    cudaGetSymbolAddress(&flag_ptr, g_flag);
    cudaMemsetAsync(flag_ptr, 0, 512 * sizeof(int));

    fused_kernel<<<64 + 1024, 768>>>(x, w1_ih0, w1_hh0, b1_0,
                                     w1_ih1, w1_hh1, b1_1,
                                     w2_ih0, w2_hh0, b2_0,
                                     w2_ih1, w2_hh1, b2_1,
                                     fc_w, fc_b, out);
}

// round 16
// speedup vs baseline: 1.9479x; 1.9479x over previous
#include <cuda_runtime.h>
#include <cstddef>

#define FULL_MASK 0xffffffffu

// ---------------------------------------------------------------------------
// packed fp32x2 FMA (sm_100+): 2x fp32 FMA throughput on Blackwell
// ---------------------------------------------------------------------------
__device__ __forceinline__ float2 ffma2(float2 a, float2 b, float2 c) {
    unsigned long long ua = *reinterpret_cast<unsigned long long*>(&a);
    unsigned long long ub = *reinterpret_cast<unsigned long long*>(&b);
    unsigned long long uc = *reinterpret_cast<unsigned long long*>(&c);
    unsigned long long ud;
    asm("fma.rn.f32x2 %0, %1, %2, %3;" : "=l"(ud) : "l"(ua), "l"(ub), "l"(uc));
    return *reinterpret_cast<float2*>(&ud);
}

// L2-coherent load: g_xg is produced by other SMs during this kernel, so it
// must not use the L1/read-only (__ldg) path.
__device__ __forceinline__ float ldcg(const float* p) {
    float v; asm volatile("ld.global.cg.f32 %0, [%1];" : "=f"(v) : "l"(p)); return v;
}

// HW tanh (sm_75+): single MUFU op, ~16 cyc vs ~56 cyc exp-based chain.
__device__ __forceinline__ float tanh_hw(float x) {
    float y; asm("tanh.approx.f32 %0, %1;" : "=f"(y) : "f"(x)); return y;
}
__device__ __forceinline__ float sigf(float x) {
    return fmaf(tanh_hw(0.5f * x), 0.5f, 0.5f);
}
__device__ __forceinline__ float tanh_fast(float x) { return tanh_hw(x); }

// Scratch: precomputed layer-1 input gates XG[B*T][256]  (64 MB)
__device__ float g_xg[64 * 1024 * 256];
// Per-m-tile completion flags: y = batch*8 + chunk; ready when flag[y] == 2
__device__ int g_flag[512];

// ---------------------------------------------------------------------------
// Fused kernel. blockIdx.x < 64  -> scan CTA (one batch each)
//               blockIdx.x >= 64 -> GEMM CTA (chunk-major tile order)
// GEMM: XG = X[65536 x 512] @ W1ih0^T[512 x 256] + b1_0, 128x128 tiles.
// Scan: round-5 proven structure: register weights, smem-broadcast h,
//       staged pre-activations, warp0 tail.
// ---------------------------------------------------------------------------
__global__ __launch_bounds__(256, 1) void fused_kernel(
    const float* __restrict__ X,
    const float* __restrict__ w1_ih0, const float* __restrict__ w1_hh0,
    const float* __restrict__ b1_0,
    const float* __restrict__ w1_ih1, const float* __restrict__ w1_hh1,
    const float* __restrict__ b1_1,
    const float* __restrict__ w2_ih0, const float* __restrict__ w2_hh0,
    const float* __restrict__ b2_0,
    const float* __restrict__ w2_ih1, const float* __restrict__ w2_hh1,
    const float* __restrict__ b2_1,
    const float* __restrict__ fc_w,  const float* __restrict__ fc_b,
    float* __restrict__ out)
{
    // ---------------- GEMM branch ----------------
    if (blockIdx.x >= 64) {
        __shared__ float As[16][132];
        __shared__ float Bs[16][132];
        const int gi = blockIdx.x - 64;          // 0..1023
        const int xnt = gi & 1;                  // n-tile
        const int r  = gi >> 1;                  // 0..511
        const int chunk = r >> 6;                // 0..7  (chunk-major order)
        const int batch = r & 63;
        const int y  = batch * 8 + chunk;        // m-tile id
        const int m0 = y * 128;
        const int n0 = xnt * 128;
        const int tid = threadIdx.x;
        const int tx = tid & 15;
        const int ty = tid >> 4;

        float2 c[8][4];
#pragma unroll
        for (int i = 0; i < 8; i++)
#pragma unroll
            for (int j = 0; j < 4; j++) c[i][j] = make_float2(0.f, 0.f);

        for (int k0 = 0; k0 < 512; k0 += 16) {
#pragma unroll
            for (int i = 0; i < 2; i++) {
                int idx = tid + i * 256;
                int row = idx >> 2;
                int kq  = (idx & 3) << 2;
                float4 va = *reinterpret_cast<const float4*>(&X[(size_t)(m0 + row) * 512 + k0 + kq]);
                As[kq + 0][row] = va.x; As[kq + 1][row] = va.y;
                As[kq + 2][row] = va.z; As[kq + 3][row] = va.w;
                float4 vb = *reinterpret_cast<const float4*>(&w1_ih0[(size_t)(n0 + row) * 512 + k0 + kq]);
                Bs[kq + 0][row] = vb.x; Bs[kq + 1][row] = vb.y;
                Bs[kq + 2][row] = vb.z; Bs[kq + 3][row] = vb.w;
            }
            __syncthreads();
#pragma unroll
            for (int kk = 0; kk < 16; kk++) {
                float4 a0 = *reinterpret_cast<const float4*>(&As[kk][ty * 8]);
                float4 a1 = *reinterpret_cast<const float4*>(&As[kk][ty * 8 + 4]);
                float4 b0 = *reinterpret_cast<const float4*>(&Bs[kk][tx * 8]);
                float4 b1 = *reinterpret_cast<const float4*>(&Bs[kk][tx * 8 + 4]);
                float  a[8]  = {a0.x, a0.y, a0.z, a0.w, a1.x, a1.y, a1.z, a1.w};
                float2 b2[4] = {make_float2(b0.x, b0.y), make_float2(b0.z, b0.w),
                                make_float2(b1.x, b1.y), make_float2(b1.z, b1.w)};
#pragma unroll
                for (int i = 0; i < 8; i++) {
                    float2 aa = make_float2(a[i], a[i]);
#pragma unroll
                    for (int j = 0; j < 4; j++)
                        c[i][j] = ffma2(aa, b2[j], c[i][j]);
                }
            }
            __syncthreads();
        }

        float4 bv0 = *reinterpret_cast<const float4*>(&b1_0[n0 + tx * 8]);
        float4 bv1 = *reinterpret_cast<const float4*>(&b1_0[n0 + tx * 8 + 4]);
#pragma unroll
        for (int i = 0; i < 8; i++) {
            int m = m0 + ty * 8 + i;
            float4 o0 = make_float4(c[i][0].x + bv0.x, c[i][0].y + bv0.y,
                                    c[i][1].x + bv0.z, c[i][1].y + bv0.w);
            float4 o1 = make_float4(c[i][2].x + bv1.x, c[i][2].y + bv1.y,
                                    c[i][3].x + bv1.z, c[i][3].y + bv1.w);
            *reinterpret_cast<float4*>(&g_xg[(size_t)m * 256 + n0 + tx * 8])     = o0;
            *reinterpret_cast<float4*>(&g_xg[(size_t)m * 256 + n0 + tx * 8 + 4]) = o1;
        }
        // publish: all stores done by all threads -> CTA sync -> gpu-scope release
        __syncthreads();
        if (tid == 0) {
            __threadfence();
            atomicAdd(&g_flag[y], 1);
        }
        return;
    }

    // ---------------- scan branch (round-5 structure) ----------------
    __shared__ float  sh_h1[64];
    __shared__ float  sh_h2[64];
    __shared__ float  sh_pre[256];
    __shared__ float  sh_h3[8];
    __shared__ float  sh_h4[8];
    __shared__ float2 sh_w2ih0T2[32 * 32];   // [k2][lane], lane<24 valid
    __shared__ float  sh_w2hh0T[6 * 32];     // [k][lane]
    __shared__ float  sh_w2ih1T[6 * 32];
    __shared__ float  sh_w2hh1T[6 * 32];
    __shared__ float  sh_fcw[36];            // row-major 6x6
    __shared__ float  sh_b20[32];
    __shared__ float  sh_b21[32];
    __shared__ float  sh_fcb[8];

    const int t = threadIdx.x;   // gate id for layers 1 & 2
    const int b = blockIdx.x;    // batch
    const int yb = b * 8;        // flag base for this batch

    // register-resident recurrent weights (fully unrolled -> stays in regs)
    float2 wA[32], wB[32], wC[32];
    {
        const float2* pa = reinterpret_cast<const float2*>(w1_hh0) + t * 32;
        const float2* pb = reinterpret_cast<const float2*>(w1_ih1) + t * 32;
        const float2* pc = reinterpret_cast<const float2*>(w1_hh1) + t * 32;
#pragma unroll
        for (int i = 0; i < 32; i++) { wA[i] = pa[i]; wB[i] = pb[i]; wC[i] = pc[i]; }
    }
    const float bias11 = b1_1[t];

    // ---- init shared state / small-layer weights ----
    if (t < 64) { sh_h1[t] = 0.f; sh_h2[t] = 0.f; }
    if (t < 8)  { sh_h3[t] = 0.f; sh_h4[t] = 0.f; sh_fcb[t] = (t < 6) ? fc_b[t] : 0.f; }
    for (int i = t; i < 1024; i += 256) {
        int k2 = i >> 5, l = i & 31;
        sh_w2ih0T2[i] = (l < 24)
            ? make_float2(w2_ih0[l * 64 + 2 * k2], w2_ih0[l * 64 + 2 * k2 + 1])
            : make_float2(0.f, 0.f);
    }
    if (t < 192) {
        int k = t / 32, l = t & 31;
        sh_w2hh0T[t] = (l < 24) ? w2_hh0[l * 6 + k] : 0.f;
        sh_w2ih1T[t] = (l < 24) ? w2_ih1[l * 6 + k] : 0.f;
        sh_w2hh1T[t] = (l < 24) ? w2_hh1[l * 6 + k] : 0.f;
    }
    if (t < 36) sh_fcw[t] = fc_w[t];
    if (t < 32) { sh_b20[t] = (t < 24) ? b2_0[t] : 0.f;
                  sh_b21[t] = (t < 24) ? b2_1[t] : 0.f; }

    // wait for chunk 0 of this batch (both n-tiles)
    if (t == 0) {
        while (atomicAdd(&g_flag[yb], 0) < 2) __nanosleep(64);
        __threadfence();
    }
    __syncthreads();

    float c1 = 0.f, c2 = 0.f, c3 = 0.f, c4 = 0.f;
    const float* xg = g_xg + ((size_t)b << 10) * 256;
    float*      outp = out + ((size_t)b << 10) * 6;
    float xg_next = ldcg(&xg[t]);

    for (int step = 0; step < 1024; step++) {
        // chunk-boundary gate for the prefetch of step+1
        if (((step + 1) & 127) == 0 && step < 1023) {
            if (t == 0) {
                int yc = yb + ((step + 1) >> 7);
                while (atomicAdd(&g_flag[yc], 0) < 2) __nanosleep(64);
                __threadfence();
            }
            __syncthreads();
        }
        float xg_cur = xg_next;
        if (step < 1023) xg_next = ldcg(&xg[(size_t)(step + 1) * 256 + t]);

        // --- phase 1: L1 pre-activations = Whh0 @ h1 + xg ---
        {
            float2 acc0 = make_float2(0.f, 0.f), acc1 = make_float2(0.f, 0.f);
            const float4* hp = reinterpret_cast<const float4*>(sh_h1);
#pragma unroll
            for (int k4 = 0; k4 < 16; k4 += 2) {
                float4 ha = hp[k4];
                float4 hb = hp[k4 + 1];
                acc0 = ffma2(wA[2 * k4 + 0], make_float2(ha.x, ha.y), acc0);
                acc1 = ffma2(wA[2 * k4 + 1], make_float2(ha.z, ha.w), acc1);
                acc0 = ffma2(wA[2 * k4 + 2], make_float2(hb.x, hb.y), acc0);
                acc1 = ffma2(wA[2 * k4 + 3], make_float2(hb.z, hb.w), acc1);
            }
            sh_pre[t] = acc0.x + acc0.y + acc1.x + acc1.y + xg_cur;
        }
        __syncthreads();   // S1

        // --- phase 3: L1 state update (t<64) + Whh1 @ h2 partial (all) ---
        float p2;
        {
            if (t < 64) {
                float gi = sigf(sh_pre[t]);
                float gf = sigf(sh_pre[64 + t]);
                float gg = tanh_fast(sh_pre[128 + t]);
                float go = sigf(sh_pre[192 + t]);
                c1 = gf * c1 + gi * gg;
                sh_h1[t] = go * tanh_fast(c1);
            }
            float2 acc0 = make_float2(0.f, 0.f), acc1 = make_float2(0.f, 0.f);
            const float4* hp = reinterpret_cast<const float4*>(sh_h2);
#pragma unroll
            for (int k4 = 0; k4 < 16; k4 += 2) {
                float4 ha = hp[k4];
                float4 hb = hp[k4 + 1];
                acc0 = ffma2(wC[2 * k4 + 0], make_float2(ha.x, ha.y), acc0);
                acc1 = ffma2(wC[2 * k4 + 1], make_float2(ha.z, ha.w), acc1);
                acc0 = ffma2(wC[2 * k4 + 2], make_float2(hb.x, hb.y), acc0);
                acc1 = ffma2(wC[2 * k4 + 3], make_float2(hb.z, hb.w), acc1);
            }
            p2 = acc0.x + acc0.y + acc1.x + acc1.y;
        }
        __syncthreads();   // S2 (h1 new visible)

        // --- phase 5: L2 pre-activations = Wih1 @ h1_new + p2 + b ---
        {
            float2 acc0 = make_float2(0.f, 0.f), acc1 = make_float2(0.f, 0.f);
            const float4* hp = reinterpret_cast<const float4*>(sh_h1);
#pragma unroll
            for (int k4 = 0; k4 < 16; k4 += 2) {
                float4 ha = hp[k4];
                float4 hb = hp[k4 + 1];
                acc0 = ffma2(wB[2 * k4 + 0], make_float2(ha.x, ha.y), acc0);
                acc1 = ffma2(wB[2 * k4 + 1], make_float2(ha.z, ha.w), acc1);
                acc0 = ffma2(wB[2 * k4 + 2], make_float2(hb.x, hb.y), acc0);
                acc1 = ffma2(wB[2 * k4 + 3], make_float2(hb.z, hb.w), acc1);
            }
            sh_pre[t] = acc0.x + acc0.y + acc1.x + acc1.y + p2 + bias11;
        }
        __syncthreads();   // S3

        // --- phase 7: L2 state update (t<64) ---
        if (t < 64) {
            float gi = sigf(sh_pre[t]);
            float gf = sigf(sh_pre[64 + t]);
            float gg = tanh_fast(sh_pre[128 + t]);
            float go = sigf(sh_pre[192 + t]);
            c2 = gf * c2 + gi * gg;
            sh_h2[t] = go * tanh_fast(c2);
        }
        __syncthreads();   // S4 (h2 new visible)

        // --- tail: layers 3, 4 + FC, warp 0 only ---
        if (t < 32) {
            const int l = t;
            // L3: gates[24] = b2_0 + W2ih0 @ h2 + W2hh0 @ h3
            float2 a0 = make_float2(0.f, 0.f), a1 = make_float2(0.f, 0.f);
            const float2* h2p = reinterpret_cast<const float2*>(sh_h2);
#pragma unroll
            for (int k2 = 0; k2 < 32; k2 += 2) {
                a0 = ffma2(sh_w2ih0T2[k2 * 32 + l],       h2p[k2],     a0);
                a1 = ffma2(sh_w2ih0T2[(k2 + 1) * 32 + l], h2p[k2 + 1], a1);
            }
            float acc = a0.x + a0.y + a1.x + a1.y + sh_b20[l];
#pragma unroll
            for (int k = 0; k < 6; k++) acc += sh_w2hh0T[k * 32 + l] * sh_h3[k];
            float vf = __shfl_sync(FULL_MASK, acc, (l + 6) & 31);
            float vg = __shfl_sync(FULL_MASK, acc, (l + 12) & 31);
            float vo = __shfl_sync(FULL_MASK, acc, (l + 18) & 31);
            if (l < 6) {
                float gi = sigf(acc), gf = sigf(vf);
                float gg = tanh_fast(vg), go = sigf(vo);
                c3 = gf * c3 + gi * gg;
                sh_h3[l] = go * tanh_fast(c3);
            }
            __syncwarp();
            // L4: gates[24] = b2_1 + W2ih1 @ h3 + W2hh1 @ h4
            float acc4 = sh_b21[l];
#pragma unroll
            for (int k = 0; k < 6; k++) {
                acc4 += sh_w2ih1T[k * 32 + l] * sh_h3[k];
                acc4 += sh_w2hh1T[k * 32 + l] * sh_h4[k];
            }
            float wf = __shfl_sync(FULL_MASK, acc4, (l + 6) & 31);
            float wg = __shfl_sync(FULL_MASK, acc4, (l + 12) & 31);
            float wo = __shfl_sync(FULL_MASK, acc4, (l + 18) & 31);
            __syncwarp();   // all reads of old sh_h4 done before overwrite
            if (l < 6) {
                float gi = sigf(acc4), gf = sigf(wf);
                float gg = tanh_fast(wg), go = sigf(wo);
                c4 = gf * c4 + gi * gg;
                sh_h4[l] = go * tanh_fast(c4);
            }
            __syncwarp();
            // FC: out[6] = fc_w @ h4 + fc_b
            if (l < 6) {
                float o = sh_fcb[l];
#pragma unroll
                for (int k = 0; k < 6; k++) o += sh_fcw[l * 6 + k] * sh_h4[k];
                outp[(size_t)step * 6 + l] = o;
            }
        }
    }
}

// ---------------------------------------------------------------------------
extern "C" void kernel_launch(void* const* d_in, const int* in_sizes, int n_in,
                              void* d_out, int out_size) {
    const float* x      = (const float*)d_in[0];
    const float* w1_ih0 = (const float*)d_in[1];
    const float* w1_hh0 = (const float*)d_in[2];
    const float* b1_0   = (const float*)d_in[3];
    const float* w1_ih1 = (const float*)d_in[4];
    const float* w1_hh1 = (const float*)d_in[5];
    const float* b1_1   = (const float*)d_in[6];
    const float* w2_ih0 = (const float*)d_in[7];
    const float* w2_hh0 = (const float*)d_in[8];
    const float* b2_0   = (const float*)d_in[9];
    const float* w2_ih1 = (const float*)d_in[10];
    const float* w2_hh1 = (const float*)d_in[11];
    const float* b2_1   = (const float*)d_in[12];
    const float* fc_w   = (const float*)d_in[13];
    const float* fc_b   = (const float*)d_in[14];
    float* out = (float*)d_out;

    // reset GEMM-tile completion flags (graph-capturable memset node)
    void* flag_ptr = nullptr;
    cudaGetSymbolAddress(&flag_ptr, g_flag);
    cudaMemsetAsync(flag_ptr, 0, 512 * sizeof(int));

    fused_kernel<<<64 + 1024, 256>>>(x, w1_ih0, w1_hh0, b1_0,
                                     w1_ih1, w1_hh1, b1_1,
                                     w2_ih0, w2_hh0, b2_0,
                                     w2_ih1, w2_hh1, b2_1,
                                     fc_w, fc_b, out);
}